// round 1
// baseline (speedup 1.0000x reference)
#include <cuda_runtime.h>

#define BB 8
#define FF 2048
#define LL 1024
#define THRESH 0.81f
#define BN_EPS 1e-5f

// scratch (device globals per allocation rules)
__device__ float g_h[BB * FF];     // h after pool, then overwritten with BN output
__device__ float g_dinv[BB * FF];  // rsqrt(degree)

// ---------------- k1: prelu + mean over L ----------------
// grid = B*F blocks, 256 threads; each thread one float4 (256*4 = 1024 = L)
__global__ void k1_rowmean(const float* __restrict__ x,
                           const float* __restrict__ w1p) {
    const float w1 = w1p[0];
    const int row = blockIdx.x;  // 0 .. B*F-1
    const float4* xr = (const float4*)(x + (size_t)row * LL);
    float4 v = xr[threadIdx.x];
    float s = 0.f;
    s += (v.x >= 0.f) ? v.x : w1 * v.x;
    s += (v.y >= 0.f) ? v.y : w1 * v.y;
    s += (v.z >= 0.f) ? v.z : w1 * v.z;
    s += (v.w >= 0.f) ? v.w : w1 * v.w;
    #pragma unroll
    for (int o = 16; o; o >>= 1) s += __shfl_down_sync(0xffffffffu, s, o);
    __shared__ float ws[8];
    const int lane = threadIdx.x & 31, wid = threadIdx.x >> 5;
    if (lane == 0) ws[wid] = s;
    __syncthreads();
    if (wid == 0) {
        s = (lane < 8) ? ws[lane] : 0.f;
        #pragma unroll
        for (int o = 4; o; o >>= 1) s += __shfl_down_sync(0xffffffffu, s, o);
        if (lane == 0) g_h[row] = s * (1.0f / LL);
    }
}

// ---------------- k2: BatchNorm over batch (per channel, biased var) ----------------
// 2048 threads total
__global__ void k2_bn(const float* __restrict__ bw, const float* __restrict__ bb) {
    const int f = blockIdx.x * blockDim.x + threadIdx.x;
    if (f >= FF) return;
    float v[BB];
    float mu = 0.f;
    #pragma unroll
    for (int b = 0; b < BB; b++) { v[b] = g_h[b * FF + f]; mu += v[b]; }
    mu *= (1.0f / BB);
    float var = 0.f;
    #pragma unroll
    for (int b = 0; b < BB; b++) { float d = v[b] - mu; var += d * d; }
    var *= (1.0f / BB);
    const float inv = rsqrtf(var + BN_EPS);
    const float w = bw[f], bi = bb[f];
    #pragma unroll
    for (int b = 0; b < BB; b++) g_h[b * FF + f] = (v[b] - mu) * inv * w + bi;
}

// ---------------- k3: degree + rsqrt ----------------
// grid (F/256, B), block 256
__global__ void k3_deg() {
    const int b = blockIdx.y;
    __shared__ float sh[FF];
    const float* hb = g_h + b * FF;
    for (int i = threadIdx.x; i < FF; i += blockDim.x) sh[i] = hb[i];
    __syncthreads();
    const int n = blockIdx.x * blockDim.x + threadIdx.x;
    const float hn = sh[n];
    float cnt = 1.0f;  // identity contribution to row sum
    #pragma unroll 8
    for (int m = 0; m < FF; m++) cnt += (hn * sh[m] > THRESH) ? 1.0f : 0.0f;
    g_dinv[b * FF + n] = rsqrtf(cnt);
}

// ---------------- k4: expand output ----------------
// out[b,n,m] = dinv_n*dinv_m*[h_n*h_m > T] + (n==m)*dinv_n^2
// grid (F/TILE_N, B), block 256; each thread owns 8 m-columns (2 float4 groups)
#define TILE_N 16
__global__ void k4_out(float* __restrict__ out) {
    const int b = blockIdx.y;
    const int n0 = blockIdx.x * TILE_N;
    const float* __restrict__ hb = g_h + b * FF;
    const float* __restrict__ db = g_dinv + b * FF;

    // per-thread m columns: q0 = tid, q1 = tid+256 (float4 indices)
    float hm[8], dm[8];
    #pragma unroll
    for (int j = 0; j < 2; j++) {
        const int q = threadIdx.x + j * 256;
        float4 h4 = ((const float4*)hb)[q];
        float4 d4 = ((const float4*)db)[q];
        hm[j * 4 + 0] = h4.x; hm[j * 4 + 1] = h4.y;
        hm[j * 4 + 2] = h4.z; hm[j * 4 + 3] = h4.w;
        dm[j * 4 + 0] = d4.x; dm[j * 4 + 1] = d4.y;
        dm[j * 4 + 2] = d4.z; dm[j * 4 + 3] = d4.w;
    }

    float* outb = out + (size_t)b * FF * FF;
    #pragma unroll 4
    for (int nn = 0; nn < TILE_N; nn++) {
        const int n = n0 + nn;
        const float hn = hb[n];        // uniform address -> broadcast, L1 hit
        const float dn = db[n];
        const float diag = dn * dn;
        float4* orow = (float4*)(outb + (size_t)n * FF);
        #pragma unroll
        for (int j = 0; j < 2; j++) {
            const int q = threadIdx.x + j * 256;
            const int mg = q * 4;
            float4 r;
            float* rp = &r.x;
            #pragma unroll
            for (int k = 0; k < 4; k++) {
                float v = (hn * hm[j * 4 + k] > THRESH) ? dn * dm[j * 4 + k] : 0.f;
                if (mg + k == n) v += diag;
                rp[k] = v;
            }
            orow[q] = r;
        }
    }
}

extern "C" void kernel_launch(void* const* d_in, const int* in_sizes, int n_in,
                              void* d_out, int out_size) {
    const float* x   = (const float*)d_in[0];
    const float* w1  = (const float*)d_in[1];
    // d_in[2] = prelu2_w: unused — A_hat is provably nonnegative, PReLU is identity
    const float* bnw = (const float*)d_in[3];
    const float* bnb = (const float*)d_in[4];
    float* out = (float*)d_out;

    k1_rowmean<<<BB * FF, 256>>>(x, w1);
    k2_bn<<<FF / 256, 256>>>(bnw, bnb);
    k3_deg<<<dim3(FF / 256, BB), 256>>>();
    k4_out<<<dim3(FF / TILE_N, BB), 256>>>(out);
}

// round 2
// speedup vs baseline: 1.1054x; 1.1054x over previous
#include <cuda_runtime.h>

#define BB 8
#define FF 2048
#define LL 1024
#define THRESH 0.81f
#define BN_EPS 1e-5f

// scratch (device globals per allocation rules)
__device__ float g_h[BB * FF];     // h after pool, then overwritten with BN output
__device__ float g_dinv[BB * FF];  // rsqrt(degree)

// ---------------- k1: prelu + mean over L ----------------
// grid = B*F blocks, 256 threads; each thread one float4 (256*4 = 1024 = L)
__global__ void k1_rowmean(const float* __restrict__ x,
                           const float* __restrict__ w1p) {
    const float w1 = w1p[0];
    const int row = blockIdx.x;  // 0 .. B*F-1
    const float4* xr = (const float4*)(x + (size_t)row * LL);
    float4 v = xr[threadIdx.x];
    float s = 0.f;
    s += (v.x >= 0.f) ? v.x : w1 * v.x;
    s += (v.y >= 0.f) ? v.y : w1 * v.y;
    s += (v.z >= 0.f) ? v.z : w1 * v.z;
    s += (v.w >= 0.f) ? v.w : w1 * v.w;
    #pragma unroll
    for (int o = 16; o; o >>= 1) s += __shfl_down_sync(0xffffffffu, s, o);
    __shared__ float ws[8];
    const int lane = threadIdx.x & 31, wid = threadIdx.x >> 5;
    if (lane == 0) ws[wid] = s;
    __syncthreads();
    if (wid == 0) {
        s = (lane < 8) ? ws[lane] : 0.f;
        #pragma unroll
        for (int o = 4; o; o >>= 1) s += __shfl_down_sync(0xffffffffu, s, o);
        if (lane == 0) g_h[row] = s * (1.0f / LL);
    }
}

// ---------------- k2: BatchNorm over batch (per channel, biased var) ----------------
__global__ void k2_bn(const float* __restrict__ bw, const float* __restrict__ bb) {
    const int f = blockIdx.x * blockDim.x + threadIdx.x;
    if (f >= FF) return;
    float v[BB];
    float mu = 0.f;
    #pragma unroll
    for (int b = 0; b < BB; b++) { v[b] = g_h[b * FF + f]; mu += v[b]; }
    mu *= (1.0f / BB);
    float var = 0.f;
    #pragma unroll
    for (int b = 0; b < BB; b++) { float d = v[b] - mu; var += d * d; }
    var *= (1.0f / BB);
    const float inv = rsqrtf(var + BN_EPS);
    const float w = bw[f], bi = bb[f];
    #pragma unroll
    for (int b = 0; b < BB; b++) g_h[b * FF + f] = (v[b] - mu) * inv * w + bi;
}

// ---------------- k3: degree + rsqrt (warp-per-row, lane-parallel) ----------------
// grid (FF/8, BB) = (256, 8) blocks, 256 threads = 8 warps; warp w handles
// row n = blockIdx.x*8 + w; lanes split the 2048 m-columns (64 float4 iters/lane... 16).
__global__ void k3_deg() {
    const int b = blockIdx.y;
    __shared__ float4 sh4[FF / 4];
    const float4* hb4 = (const float4*)(g_h + b * FF);
    #pragma unroll
    for (int i = threadIdx.x; i < FF / 4; i += 256) sh4[i] = hb4[i];
    __syncthreads();

    const int warp = threadIdx.x >> 5, lane = threadIdx.x & 31;
    const int n = blockIdx.x * 8 + warp;
    const float hn = g_h[b * FF + n];  // uniform per warp -> broadcast
    float cnt = 0.f;
    #pragma unroll 4
    for (int i = lane; i < FF / 4; i += 32) {
        float4 v = sh4[i];
        // exact same FMUL-then-compare semantics as reference sim > THRESH
        cnt += (hn * v.x > THRESH) ? 1.f : 0.f;
        cnt += (hn * v.y > THRESH) ? 1.f : 0.f;
        cnt += (hn * v.z > THRESH) ? 1.f : 0.f;
        cnt += (hn * v.w > THRESH) ? 1.f : 0.f;
    }
    #pragma unroll
    for (int o = 16; o; o >>= 1) cnt += __shfl_down_sync(0xffffffffu, cnt, o);
    if (lane == 0) g_dinv[b * FF + n] = rsqrtf(cnt + 1.0f);  // +1 for identity
}

// ---------------- k4: expand output ----------------
// out[b,n,m] = dinv_n*dinv_m*[h_n*h_m > T] + (n==m)*dinv_n^2
// grid (F/TILE_N, B), block 256; each thread owns 8 m-columns (2 float4 groups)
#define TILE_N 32
__global__ void k4_out(float* __restrict__ out) {
    const int b = blockIdx.y;
    const int n0 = blockIdx.x * TILE_N;
    const float* __restrict__ hb = g_h + b * FF;
    const float* __restrict__ db = g_dinv + b * FF;

    // per-thread m columns: q0 = tid, q1 = tid+256 (float4 indices)
    float hm[8], dm[8];
    #pragma unroll
    for (int j = 0; j < 2; j++) {
        const int q = threadIdx.x + j * 256;
        float4 h4 = ((const float4*)hb)[q];
        float4 d4 = ((const float4*)db)[q];
        hm[j * 4 + 0] = h4.x; hm[j * 4 + 1] = h4.y;
        hm[j * 4 + 2] = h4.z; hm[j * 4 + 3] = h4.w;
        dm[j * 4 + 0] = d4.x; dm[j * 4 + 1] = d4.y;
        dm[j * 4 + 2] = d4.z; dm[j * 4 + 3] = d4.w;
    }

    float* outb = out + (size_t)b * FF * FF;
    #pragma unroll 4
    for (int nn = 0; nn < TILE_N; nn++) {
        const int n = n0 + nn;
        const float hn = hb[n];        // uniform address -> broadcast, L1 hit
        const float dn = db[n];
        const float diag = dn * dn;
        float4* orow = (float4*)(outb + (size_t)n * FF);
        #pragma unroll
        for (int j = 0; j < 2; j++) {
            const int q = threadIdx.x + j * 256;
            const int mg = q * 4;
            float4 r;
            float* rp = &r.x;
            #pragma unroll
            for (int k = 0; k < 4; k++) {
                float v = (hn * hm[j * 4 + k] > THRESH) ? dn * dm[j * 4 + k] : 0.f;
                if (mg + k == n) v += diag;
                rp[k] = v;
            }
            orow[q] = r;
        }
    }
}

extern "C" void kernel_launch(void* const* d_in, const int* in_sizes, int n_in,
                              void* d_out, int out_size) {
    const float* x   = (const float*)d_in[0];
    const float* w1  = (const float*)d_in[1];
    // d_in[2] = prelu2_w: unused — A_hat is provably nonnegative, PReLU is identity
    const float* bnw = (const float*)d_in[3];
    const float* bnb = (const float*)d_in[4];
    float* out = (float*)d_out;

    k1_rowmean<<<BB * FF, 256>>>(x, w1);
    k2_bn<<<FF / 256, 256>>>(bnw, bnb);
    k3_deg<<<dim3(FF / 8, BB), 256>>>();
    k4_out<<<dim3(FF / TILE_N, BB), 256>>>(out);
}

// round 3
// speedup vs baseline: 1.2000x; 1.0856x over previous
#include <cuda_runtime.h>

#define BB 8
#define FF 2048
#define LL 1024
#define THRESH 0.81f
#define BN_EPS 1e-5f

// scratch (device globals per allocation rules)
__device__ float g_h[BB * FF];     // h after pool, then overwritten with BN output
__device__ float g_dinv[BB * FF];  // rsqrt(degree)

// ---------------- k1: prelu + mean over L (warp-per-row) ----------------
// grid = BB*FF/8 = 2048 blocks, 256 threads = 8 warps.
// Warp w reduces row blockIdx.x*8 + w: each lane loads 8 float4 (front-batched,
// MLP=8), prelu+sum, then shuffle reduce. No smem, no __syncthreads.
__global__ void k1_rowmean(const float* __restrict__ x,
                           const float* __restrict__ w1p) {
    const float w1 = w1p[0];
    const int warp = threadIdx.x >> 5, lane = threadIdx.x & 31;
    const int row = blockIdx.x * 8 + warp;
    const float4* xr = (const float4*)(x + (size_t)row * LL);

    float4 v[8];
    #pragma unroll
    for (int j = 0; j < 8; j++) v[j] = xr[lane + 32 * j];

    float s = 0.f;
    #pragma unroll
    for (int j = 0; j < 8; j++) {
        s += (v[j].x >= 0.f) ? v[j].x : w1 * v[j].x;
        s += (v[j].y >= 0.f) ? v[j].y : w1 * v[j].y;
        s += (v[j].z >= 0.f) ? v[j].z : w1 * v[j].z;
        s += (v[j].w >= 0.f) ? v[j].w : w1 * v[j].w;
    }
    #pragma unroll
    for (int o = 16; o; o >>= 1) s += __shfl_down_sync(0xffffffffu, s, o);
    if (lane == 0) g_h[row] = s * (1.0f / LL);
}

// ---------------- k2: BatchNorm over batch (per channel, biased var) ----------------
__global__ void k2_bn(const float* __restrict__ bw, const float* __restrict__ bb) {
    const int f = blockIdx.x * blockDim.x + threadIdx.x;
    if (f >= FF) return;
    float v[BB];
    float mu = 0.f;
    #pragma unroll
    for (int b = 0; b < BB; b++) { v[b] = g_h[b * FF + f]; mu += v[b]; }
    mu *= (1.0f / BB);
    float var = 0.f;
    #pragma unroll
    for (int b = 0; b < BB; b++) { float d = v[b] - mu; var += d * d; }
    var *= (1.0f / BB);
    const float inv = rsqrtf(var + BN_EPS);
    const float w = bw[f], bi = bb[f];
    #pragma unroll
    for (int b = 0; b < BB; b++) g_h[b * FF + f] = (v[b] - mu) * inv * w + bi;
}

// ---------------- k3: degree + rsqrt (warp-per-row, lane-parallel) ----------------
// grid (FF/8, BB), 256 threads = 8 warps; warp w handles row n = blockIdx.x*8 + w.
__global__ void k3_deg() {
    const int b = blockIdx.y;
    __shared__ float4 sh4[FF / 4];
    const float4* hb4 = (const float4*)(g_h + b * FF);
    #pragma unroll
    for (int i = threadIdx.x; i < FF / 4; i += 256) sh4[i] = hb4[i];
    __syncthreads();

    const int warp = threadIdx.x >> 5, lane = threadIdx.x & 31;
    const int n = blockIdx.x * 8 + warp;
    const float hn = g_h[b * FF + n];  // uniform per warp -> broadcast
    float cnt = 0.f;
    #pragma unroll 4
    for (int i = lane; i < FF / 4; i += 32) {
        float4 v = sh4[i];
        // exact same FMUL-then-compare semantics as reference sim > THRESH
        cnt += (hn * v.x > THRESH) ? 1.f : 0.f;
        cnt += (hn * v.y > THRESH) ? 1.f : 0.f;
        cnt += (hn * v.z > THRESH) ? 1.f : 0.f;
        cnt += (hn * v.w > THRESH) ? 1.f : 0.f;
    }
    #pragma unroll
    for (int o = 16; o; o >>= 1) cnt += __shfl_down_sync(0xffffffffu, cnt, o);
    if (lane == 0) g_dinv[b * FF + n] = rsqrtf(cnt + 1.0f);  // +1 for identity
}

// ---------------- k4: expand output ----------------
// out[b,n,m] = dinv_n*dinv_m*[h_n*h_m > T] + (n==m)*dinv_n^2
// grid (F/TILE_N, B), block 256; each thread owns 8 m-columns (2 float4 groups)
#define TILE_N 16
__global__ void k4_out(float* __restrict__ out) {
    const int b = blockIdx.y;
    const int n0 = blockIdx.x * TILE_N;
    const float* __restrict__ hb = g_h + b * FF;
    const float* __restrict__ db = g_dinv + b * FF;

    // per-thread m columns: q0 = tid, q1 = tid+256 (float4 indices)
    float hm[8], dm[8];
    #pragma unroll
    for (int j = 0; j < 2; j++) {
        const int q = threadIdx.x + j * 256;
        float4 h4 = ((const float4*)hb)[q];
        float4 d4 = ((const float4*)db)[q];
        hm[j * 4 + 0] = h4.x; hm[j * 4 + 1] = h4.y;
        hm[j * 4 + 2] = h4.z; hm[j * 4 + 3] = h4.w;
        dm[j * 4 + 0] = d4.x; dm[j * 4 + 1] = d4.y;
        dm[j * 4 + 2] = d4.z; dm[j * 4 + 3] = d4.w;
    }

    float* outb = out + (size_t)b * FF * FF;
    #pragma unroll 4
    for (int nn = 0; nn < TILE_N; nn++) {
        const int n = n0 + nn;
        const float hn = hb[n];        // uniform address -> broadcast, L1 hit
        const float dn = db[n];
        const float diag = dn * dn;
        float4* orow = (float4*)(outb + (size_t)n * FF);
        #pragma unroll
        for (int j = 0; j < 2; j++) {
            const int q = threadIdx.x + j * 256;
            const int mg = q * 4;
            float4 r;
            float* rp = &r.x;
            #pragma unroll
            for (int k = 0; k < 4; k++) {
                float v = (hn * hm[j * 4 + k] > THRESH) ? dn * dm[j * 4 + k] : 0.f;
                if (mg + k == n) v += diag;
                rp[k] = v;
            }
            orow[q] = r;
        }
    }
}

extern "C" void kernel_launch(void* const* d_in, const int* in_sizes, int n_in,
                              void* d_out, int out_size) {
    const float* x   = (const float*)d_in[0];
    const float* w1  = (const float*)d_in[1];
    // d_in[2] = prelu2_w: unused — A_hat is provably nonnegative, PReLU is identity
    const float* bnw = (const float*)d_in[3];
    const float* bnb = (const float*)d_in[4];
    float* out = (float*)d_out;

    k1_rowmean<<<BB * FF / 8, 256>>>(x, w1);
    k2_bn<<<FF / 256, 256>>>(bnw, bnb);
    k3_deg<<<dim3(FF / 8, BB), 256>>>();
    k4_out<<<dim3(FF / TILE_N, BB), 256>>>(out);
}

// round 4
// speedup vs baseline: 1.2598x; 1.0499x over previous
#include <cuda_runtime.h>
#include <cstdint>

#define BB 8
#define FF 2048
#define LL 1024
#define THRESH 0.81f
#define BN_EPS 1e-5f

// scratch (device globals per allocation rules)
__device__ float g_h[BB * FF];     // raw pooled prelu means (k1 output)
__device__ float g_hbn[BB * FF];   // BN'd h (k23 output)
__device__ float g_dinv[BB * FF];  // rsqrt(degree)

// ---------------- k1: prelu + mean over L (warp-per-row) ----------------
// grid = BB*FF/8 = 2048 blocks, 256 threads = 8 warps. MLP=8 per lane.
__global__ void k1_rowmean(const float* __restrict__ x,
                           const float* __restrict__ w1p) {
    const float w1 = w1p[0];
    const int warp = threadIdx.x >> 5, lane = threadIdx.x & 31;
    const int row = blockIdx.x * 8 + warp;
    const float4* xr = (const float4*)(x + (size_t)row * LL);

    float4 v[8];
    #pragma unroll
    for (int j = 0; j < 8; j++) v[j] = xr[lane + 32 * j];

    float s = 0.f;
    #pragma unroll
    for (int j = 0; j < 8; j++) {
        s += (v[j].x >= 0.f) ? v[j].x : w1 * v[j].x;
        s += (v[j].y >= 0.f) ? v[j].y : w1 * v[j].y;
        s += (v[j].z >= 0.f) ? v[j].z : w1 * v[j].z;
        s += (v[j].w >= 0.f) ? v[j].w : w1 * v[j].w;
    }
    #pragma unroll
    for (int o = 16; o; o >>= 1) s += __shfl_down_sync(0xffffffffu, s, o);
    if (lane == 0) g_h[row] = s * (1.0f / LL);
}

// ---------------- k23: fused BatchNorm + degree ----------------
// grid (FF/64, BB) = (32, 8) = 256 blocks, 512 threads = 16 warps.
// Each block redundantly computes BN for ALL channels of batch b into smem
// (L2-hit loads, trivial), writes its own 64-column slice of g_hbn, then
// warp w counts degree for rows bx*64 + w*4 .. +3 against smem.
#define SLICE 64
__global__ void k23_bn_deg(const float* __restrict__ bw,
                           const float* __restrict__ bb) {
    const int b = blockIdx.y;
    __shared__ float sh[FF];
    const int tid = threadIdx.x;

    // BN: 4 channels per thread (coalesced, f = tid + c*512)
    #pragma unroll
    for (int c = 0; c < 4; c++) {
        const int f = tid + c * 512;
        float v[BB];
        float mu = 0.f;
        #pragma unroll
        for (int q = 0; q < BB; q++) { v[q] = g_h[q * FF + f]; mu += v[q]; }
        mu *= (1.0f / BB);
        float var = 0.f;
        #pragma unroll
        for (int q = 0; q < BB; q++) { float d = v[q] - mu; var += d * d; }
        var *= (1.0f / BB);
        const float hv = (v[b] - mu) * rsqrtf(var + BN_EPS) * bw[f] + bb[f];
        sh[f] = hv;
        if ((f >> 6) == (int)blockIdx.x) g_hbn[b * FF + f] = hv;
    }
    __syncthreads();

    // degree count: warp w -> 4 rows
    const int warp = tid >> 5, lane = tid & 31;
    const int nbase = blockIdx.x * SLICE + warp * 4;
    float hn[4], cnt[4] = {0.f, 0.f, 0.f, 0.f};
    #pragma unroll
    for (int r = 0; r < 4; r++) hn[r] = sh[nbase + r];

    const float4* s4 = (const float4*)sh;
    #pragma unroll 4
    for (int i = lane; i < FF / 4; i += 32) {
        float4 v = s4[i];
        #pragma unroll
        for (int r = 0; r < 4; r++) {
            cnt[r] += (hn[r] * v.x > THRESH) ? 1.f : 0.f;
            cnt[r] += (hn[r] * v.y > THRESH) ? 1.f : 0.f;
            cnt[r] += (hn[r] * v.z > THRESH) ? 1.f : 0.f;
            cnt[r] += (hn[r] * v.w > THRESH) ? 1.f : 0.f;
        }
    }
    #pragma unroll
    for (int r = 0; r < 4; r++) {
        #pragma unroll
        for (int o = 16; o; o >>= 1)
            cnt[r] += __shfl_down_sync(0xffffffffu, cnt[r], o);
    }
    if (lane == 0) {
        #pragma unroll
        for (int r = 0; r < 4; r++)
            g_dinv[b * FF + nbase + r] = rsqrtf(cnt[r] + 1.0f);  // +1 identity
    }
}

// ---------------- k4: expand output via smem staging + 1D bulk TMA store ----
// out[b,n,m] = dinv_n*dinv_m*[h_n*h_m > T] + (n==m)*dinv_n^2
// grid (FF/TILE_N, BB), 256 threads. Tile of TILE_N=4 contiguous rows (32KB)
// built in smem, then one cp.async.bulk store (bypasses L1 store path).
#define TILE_N 4
__global__ void k4_out(float* __restrict__ out) {
    __shared__ __align__(128) float tile[TILE_N * FF];  // 32 KB
    const int b = blockIdx.y;
    const int n0 = blockIdx.x * TILE_N;
    const float* __restrict__ hb = g_hbn + b * FF;
    const float* __restrict__ db = g_dinv + b * FF;

    // per-thread m columns: float4 indices q0 = tid, q1 = tid+256
    float hm[8], dm[8];
    #pragma unroll
    for (int j = 0; j < 2; j++) {
        const int q = threadIdx.x + j * 256;
        float4 h4 = ((const float4*)hb)[q];
        float4 d4 = ((const float4*)db)[q];
        hm[j * 4 + 0] = h4.x; hm[j * 4 + 1] = h4.y;
        hm[j * 4 + 2] = h4.z; hm[j * 4 + 3] = h4.w;
        dm[j * 4 + 0] = d4.x; dm[j * 4 + 1] = d4.y;
        dm[j * 4 + 2] = d4.z; dm[j * 4 + 3] = d4.w;
    }

    float4* t4 = (float4*)tile;
    #pragma unroll
    for (int nn = 0; nn < TILE_N; nn++) {
        const int n = n0 + nn;
        const float hn = hb[n];        // uniform -> broadcast, L1 hit
        const float dn = db[n];
        const float diag = dn * dn;
        #pragma unroll
        for (int j = 0; j < 2; j++) {
            const int q = threadIdx.x + j * 256;
            const int mg = q * 4;
            float4 r;
            float* rp = &r.x;
            #pragma unroll
            for (int k = 0; k < 4; k++) {
                float v = (hn * hm[j * 4 + k] > THRESH) ? dn * dm[j * 4 + k] : 0.f;
                if (mg + k == n) v += diag;
                rp[k] = v;
            }
            t4[nn * (FF / 4) + q] = r;
        }
    }
    __syncthreads();

    if (threadIdx.x == 0) {
        asm volatile("fence.proxy.async.shared::cta;" ::: "memory");
        uint32_t saddr;
        asm("{ .reg .u64 t; cvta.to.shared.u64 t, %1; cvt.u32.u64 %0, t; }"
            : "=r"(saddr) : "l"(tile));
        float* gdst = out + (size_t)b * FF * FF + (size_t)n0 * FF;
        const unsigned bytes = TILE_N * FF * 4;  // 32768
        asm volatile(
            "cp.async.bulk.global.shared::cta.bulk_group [%0], [%1], %2;"
            :: "l"(gdst), "r"(saddr), "r"(bytes) : "memory");
        asm volatile("cp.async.bulk.commit_group;" ::: "memory");
        asm volatile("cp.async.bulk.wait_group.read 0;" ::: "memory");
    }
}

extern "C" void kernel_launch(void* const* d_in, const int* in_sizes, int n_in,
                              void* d_out, int out_size) {
    const float* x   = (const float*)d_in[0];
    const float* w1  = (const float*)d_in[1];
    // d_in[2] = prelu2_w: unused — A_hat is provably nonnegative, PReLU is identity
    const float* bnw = (const float*)d_in[3];
    const float* bnb = (const float*)d_in[4];
    float* out = (float*)d_out;

    k1_rowmean<<<BB * FF / 8, 256>>>(x, w1);
    k23_bn_deg<<<dim3(FF / SLICE, BB), 512>>>(bnw, bnb);
    k4_out<<<dim3(FF / TILE_N, BB), 256>>>(out);
}